// round 10
// baseline (speedup 1.0000x reference)
#include <cuda_runtime.h>
#include <cstdint>
#include <cstddef>

#define S_LEN 2048
#define BATCH 512
#define VDIM  29
#define HDIM  128
#define NWARP 8              // k-split chunks per row-pair
#define KC    (HDIM / NWARP) // 16 k's per chunk (recurrent K = 128, x hoisted)
#define ROWS  4              // batch rows per CTA
#define XBT   64             // (b,t) pairs per xp block

// static device scratch (allocation-free per rules)
__device__ float g_enc[BATCH * HDIM];
__device__ float g_xp[(size_t)BATCH * S_LEN * HDIM];   // 512 MB: x @ We_ih^T + biases

typedef unsigned long long ull;

__device__ __forceinline__ ull pack2(float lo, float hi) {
    ull r; asm("mov.b64 %0, {%1, %2};" : "=l"(r) : "f"(lo), "f"(hi)); return r;
}
__device__ __forceinline__ ull fma2(ull a, ull b, ull c) {
    ull d; asm("fma.rn.f32x2 %0, %1, %2, %3;" : "=l"(d) : "l"(a), "l"(b), "l"(c)); return d;
}
__device__ __forceinline__ void unpack2(ull v, float& lo, float& hi) {
    asm("mov.b64 {%0, %1}, %2;" : "=f"(lo), "=f"(hi) : "l"(v));
}
__device__ __forceinline__ float fast_tanh(float x) {
    float ax = fabsf(x);
    float t  = __expf(-2.0f * ax);                 // MUFU.EX2 path
    float r  = __fdividef(1.0f - t, 1.0f + t);     // MUFU.RCP path
    return copysignf(r, x);
}

// ---------------------------------------------------------------------------
// xp precompute: xp[b][t][j] = sum_v x[b][t][v]*We_ih[j][v] + be_ih[j] + be_hh[j]
// L1tex fix vs R9: xs rows padded to 32 floats, read as 8 LDS.128 per (b,t)
// instead of 29 scalar LDS; W row zero-padded to 32 in registers.
// ---------------------------------------------------------------------------
__global__ void __launch_bounds__(128) xp_kernel(
    const float* __restrict__ x, const float* __restrict__ We_ih,
    const float* __restrict__ be_ih, const float* __restrict__ be_hh)
{
    __shared__ float xs[XBT][32];              // padded rows (v=29..31 zero)
    const int j = threadIdx.x;
    const size_t bt0 = (size_t)blockIdx.x * XBT;

    for (int i = j; i < XBT * VDIM; i += 128) {
        int b = i / VDIM, v = i - b * VDIM;
        xs[b][v] = x[bt0 * VDIM + i];
    }
    for (int i = j; i < XBT * 3; i += 128) xs[i / 3][VDIM + i % 3] = 0.f;

    float wr[32];
    #pragma unroll
    for (int v = 0; v < 32; ++v) wr[v] = (v < VDIM) ? We_ih[j * VDIM + v] : 0.f;
    const float bias = be_ih[j] + be_hh[j];
    __syncthreads();

    #pragma unroll 2
    for (int b = 0; b < XBT; ++b) {
        float s0 = bias, s1 = 0.f, s2 = 0.f, s3 = 0.f;
        #pragma unroll
        for (int c = 0; c < 8; ++c) {
            const float4 xv = *(const float4*)(&xs[b][4 * c]);   // LDS.128
            s0 = fmaf(xv.x, wr[4 * c],     s0);
            s1 = fmaf(xv.y, wr[4 * c + 1], s1);
            s2 = fmaf(xv.z, wr[4 * c + 2], s2);
            s3 = fmaf(xv.w, wr[4 * c + 3], s3);
        }
        g_xp[(bt0 + b) * HDIM + j] = (s0 + s1) + (s2 + s3);
    }
}

// ---------------------------------------------------------------------------
// Encoder: R7's proven structure (single __syncthreads pair, 16 warps) with
// recurrent K=128 (x-projection hoisted to g_xp) and MUFU-based tanh.
// 128 CTAs x 4 rows x 512 threads. Warp w: chunk=w&7 owns k in [chunk*16,+16),
// rowpair rp=w>>3 owns rows (2rp, 2rp+1). Weight col-pairs in registers;
// state duplicated (h0,h0,h1,h1) so one LDS.128 per k feeds 4 fma2.
// 8-way k-partials reduced in SMEM by all 512 threads (128 j x 4 rows).
// ---------------------------------------------------------------------------
__global__ void __launch_bounds__(512, 1) enc_kernel(const float* __restrict__ We_hh)
{
    extern __shared__ float sm[];
    float* Wt  = sm;                      // [HDIM][HDIM] k-major staging
    float* gb  = Wt + HDIM * HDIM;        // [2 buf][2 rowpair][HDIM][4] dup state
    float* red = gb + 2 * 2 * HDIM * 4;   // [NWARP][4 rows][HDIM] partials

    const int tid  = threadIdx.x;
    const int warp = tid >> 5, lane = tid & 31;
    const int chunk = warp & 7;
    const int rp    = warp >> 3;          // 0: rows 0,1   1: rows 2,3
    const int rowbase = blockIdx.x * ROWS;

    // Stage We_hh k-major, zero both state buffers
    for (int i = tid; i < HDIM * HDIM; i += 512) {
        int k = i >> 7, j = i & (HDIM - 1);
        Wt[i] = We_hh[j * HDIM + k];
    }
    for (int i = tid; i < 2 * 2 * HDIM * 4; i += 512) gb[i] = 0.f;   // h = 0
    __syncthreads();

    const int k0 = chunk * KC;
    ull wlo[KC], whi[KC];                 // pre-packed col pairs (64 regs)
    #pragma unroll
    for (int kk = 0; kk < KC; ++kk) {
        const float4 w4 = *(const float4*)(Wt + (k0 + kk) * HDIM + 4 * lane);
        wlo[kk] = pack2(w4.x, w4.y);
        whi[kk] = pack2(w4.z, w4.w);
    }
    __syncthreads();

    // finalize mapping: 512 threads = 128 j x 4 rows
    const int jf = tid & (HDIM - 1);
    const int rr = tid >> 7;              // row 0..3
    const size_t xbase = ((size_t)(rowbase + rr) * S_LEN) * HDIM + jf;
    float xcur = g_xp[xbase];             // xp for t=0

    for (int t = 0; t < S_LEN; ++t) {
        const int bo = (t & 1) * (2 * HDIM * 4);
        const int bn = bo ^ (2 * HDIM * 4);

        // prefetch next step's xp (DRAM latency hidden under the GEMV)
        float xnext = 0.f;
        if (t + 1 < S_LEN) xnext = g_xp[xbase + (size_t)(t + 1) * HDIM];

        ull aL0 = 0, aH0 = 0, aL1 = 0, aH1 = 0;
        const float* gk = gb + bo + (rp * HDIM + k0) * 4;
        #pragma unroll
        for (int kk = 0; kk < KC; ++kk) {
            const ulonglong2 gg = *(const ulonglong2*)(gk + kk * 4);  // 1 LDS.128
            aL0 = fma2(wlo[kk], gg.x, aL0); aH0 = fma2(whi[kk], gg.x, aH0);
            aL1 = fma2(wlo[kk], gg.y, aL1); aH1 = fma2(whi[kk], gg.y, aH1);
        }
        float q0, q1, q2, q3, q4, q5, q6, q7;
        unpack2(aL0, q0, q1); unpack2(aH0, q2, q3);
        unpack2(aL1, q4, q5); unpack2(aH1, q6, q7);
        {   // store k-partials, conflict-free STS.128
            float* rb = red + (chunk * 4 + rp * 2) * HDIM + 4 * lane;
            *(float4*)(rb)        = make_float4(q0, q1, q2, q3);
            *(float4*)(rb + HDIM) = make_float4(q4, q5, q6, q7);
        }
        __syncthreads();

        // finalize: 512 threads, each sums 8 partials for (jf, rr), tanh
        {
            float s = xcur;
            #pragma unroll
            for (int c = 0; c < NWARP; ++c)
                s += red[(c * 4 + rr) * HDIM + jf];
            float h = fast_tanh(s);
            *(float2*)(gb + bn + ((rr >> 1) * HDIM + jf) * 4 + 2 * (rr & 1)) =
                make_float2(h, h);
            if (t == S_LEN - 1) g_enc[(rowbase + rr) * HDIM + jf] = h;
        }
        xcur = xnext;
        __syncthreads();
    }
}

// ---------------------------------------------------------------------------
// Decoder (unchanged from R9): one warp per batch row, 128 CTAs x 4 warps.
// h in per-warp double-buffered SMEM (broadcast LDS.128), 8 FMA accumulators,
// MUFU-based tanh. W row padded to 32 with zeros.
// ---------------------------------------------------------------------------
__global__ void __launch_bounds__(128) dec_kernel(
    const float* __restrict__ Wd_ih, const float* __restrict__ Wd_hh,
    const float* __restrict__ bd_ih, const float* __restrict__ bd_hh,
    float* __restrict__ out)
{
    __shared__ float hbuf[2][4][32];
    const int warp = threadIdx.x >> 5, lane = threadIdx.x & 31;
    const int b = blockIdx.x * 4 + warp;
    const float* er = g_enc + b * HDIM;
    float e0 = er[lane], e1 = er[32 + lane], e2 = er[64 + lane], e3 = er[96 + lane];
    const bool act = lane < VDIM;
    const int vl = act ? lane : 0;

    float Wp[32];
    #pragma unroll
    for (int u = 0; u < 32; ++u) Wp[u] = (u < VDIM) ? Wd_hh[vl * VDIM + u] : 0.f;

    float din = bd_ih[vl] + bd_hh[vl];
    {
        const float* wi = Wd_ih + vl * HDIM;
        float s0 = 0, s1 = 0, s2 = 0, s3 = 0;
        #pragma unroll
        for (int k = 0; k < 32; ++k) {
            s0 += wi[k]      * __shfl_sync(0xffffffffu, e0, k);
            s1 += wi[32 + k] * __shfl_sync(0xffffffffu, e1, k);
            s2 += wi[64 + k] * __shfl_sync(0xffffffffu, e2, k);
            s3 += wi[96 + k] * __shfl_sync(0xffffffffu, e3, k);
        }
        din += (s0 + s1) + (s2 + s3);
    }

    hbuf[0][warp][lane] = 0.f;
    __syncwarp();

    float* orow = out + (size_t)b * S_LEN * VDIM + lane;
    for (int s = 0; s < S_LEN; ++s) {
        const float* hv = hbuf[s & 1][warp];
        const float4 A = *(const float4*)(hv);
        const float4 B = *(const float4*)(hv + 4);
        const float4 C = *(const float4*)(hv + 8);
        const float4 D = *(const float4*)(hv + 12);
        const float4 E = *(const float4*)(hv + 16);
        const float4 F = *(const float4*)(hv + 20);
        const float4 G = *(const float4*)(hv + 24);
        const float4 H = *(const float4*)(hv + 28);
        float q0 = fmaf(Wp[0],  A.x, din), q1 = Wp[1]  * A.y;
        float q2 = Wp[2]  * A.z,           q3 = Wp[3]  * A.w;
        float q4 = Wp[4]  * B.x,           q5 = Wp[5]  * B.y;
        float q6 = Wp[6]  * B.z,           q7 = Wp[7]  * B.w;
        q0 = fmaf(Wp[8],  C.x, q0); q1 = fmaf(Wp[9],  C.y, q1);
        q2 = fmaf(Wp[10], C.z, q2); q3 = fmaf(Wp[11], C.w, q3);
        q4 = fmaf(Wp[12], D.x, q4); q5 = fmaf(Wp[13], D.y, q5);
        q6 = fmaf(Wp[14], D.z, q6); q7 = fmaf(Wp[15], D.w, q7);
        q0 = fmaf(Wp[16], E.x, q0); q1 = fmaf(Wp[17], E.y, q1);
        q2 = fmaf(Wp[18], E.z, q2); q3 = fmaf(Wp[19], E.w, q3);
        q4 = fmaf(Wp[20], F.x, q4); q5 = fmaf(Wp[21], F.y, q5);
        q6 = fmaf(Wp[22], F.z, q6); q7 = fmaf(Wp[23], F.w, q7);
        q0 = fmaf(Wp[24], G.x, q0); q1 = fmaf(Wp[25], G.y, q1);
        q2 = fmaf(Wp[26], G.z, q2); q3 = fmaf(Wp[27], G.w, q3);
        q4 = fmaf(Wp[28], H.x, q4); q5 = fmaf(Wp[29], H.y, q5);
        q6 = fmaf(Wp[30], H.z, q6); q7 = fmaf(Wp[31], H.w, q7);
        float hn = fast_tanh(((q0 + q1) + (q2 + q3)) + ((q4 + q5) + (q6 + q7)));
        hbuf[(s & 1) ^ 1][warp][lane] = hn;
        if (act) orow[(size_t)s * VDIM] = hn;
        __syncwarp();
    }
}

// ---------------------------------------------------------------------------
extern "C" void kernel_launch(void* const* d_in, const int* in_sizes, int n_in,
                              void* d_out, int out_size) {
    const float* x     = (const float*)d_in[0];
    const float* We_ih = (const float*)d_in[1];
    const float* We_hh = (const float*)d_in[2];
    const float* be_ih = (const float*)d_in[3];
    const float* be_hh = (const float*)d_in[4];
    const float* Wd_ih = (const float*)d_in[5];
    const float* Wd_hh = (const float*)d_in[6];
    const float* bd_ih = (const float*)d_in[7];
    const float* bd_hh = (const float*)d_in[8];
    float* out = (float*)d_out;

    const int smem = (HDIM * HDIM + 2 * 2 * HDIM * 4 + NWARP * 4 * HDIM) * 4; // 90112 B
    cudaFuncSetAttribute(enc_kernel, cudaFuncAttributeMaxDynamicSharedMemorySize, smem);

    xp_kernel<<<(BATCH * S_LEN) / XBT, 128>>>(x, We_ih, be_ih, be_hh);
    enc_kernel<<<BATCH / ROWS, 512, smem>>>(We_hh);
    dec_kernel<<<BATCH / 4, 128>>>(Wd_ih, Wd_hh, bd_ih, bd_hh, out);
}

// round 12
// speedup vs baseline: 1.3688x; 1.3688x over previous
#include <cuda_runtime.h>
#include <cstdint>
#include <cstddef>

#define S_LEN 2048
#define BATCH 512
#define VDIM  29
#define HDIM  128
#define KTOT  160            // 128 (h) + 29 (x) padded to 160 — x inline (no xp kernel)
#define NWARP 8              // k-split chunks per row-pair
#define KC    (KTOT / NWARP) // 20 k's per chunk
#define ROWS  4              // batch rows per CTA

// intermediate encoder state (static device scratch — no allocation)
__device__ float g_enc[BATCH * HDIM];

typedef unsigned long long ull;

__device__ __forceinline__ ull pack2(float lo, float hi) {
    ull r; asm("mov.b64 %0, {%1, %2};" : "=l"(r) : "f"(lo), "f"(hi)); return r;
}
__device__ __forceinline__ ull fma2(ull a, ull b, ull c) {
    ull d; asm("fma.rn.f32x2 %0, %1, %2, %3;" : "=l"(d) : "l"(a), "l"(b), "l"(c)); return d;
}
__device__ __forceinline__ float fast_tanh(float x) {
    float ax = fabsf(x);
    float t  = __expf(-2.0f * ax);                 // MUFU.EX2 path
    float r  = __fdividef(1.0f - t, 1.0f + t);     // MUFU.RCP path
    return copysignf(r, x);
}

// ---------------------------------------------------------------------------
// Encoder: R7's proven structure (best measured), K=160 inline x.
// 128 CTAs x 4 rows x 512 threads. Warp w: chunk=w&7 owns k in [chunk*20,+20),
// rowpair rp=w>>3 owns rows (2rp, 2rp+1). Weight col-pairs in registers;
// state duplicated (h0,h0,h1,h1) so one LDS.128 per k feeds 4 fma2.
// Deltas vs R7: MUFU-based tanh in finalize (validated ~3e-7), bias held in
// a register, and partials stored as raw ulonglong2 accumulator pairs
// (no unpack/repack MOVs). 8-way k-partials reduced by all 512 threads.
// ---------------------------------------------------------------------------
__global__ void __launch_bounds__(512, 1) enc_kernel(
    const float* __restrict__ x, const float* __restrict__ We_ih,
    const float* __restrict__ We_hh, const float* __restrict__ be_ih,
    const float* __restrict__ be_hh)
{
    extern __shared__ float sm[];
    float* Wt  = sm;                      // [KTOT][HDIM] k-major staging
    float* gb  = Wt + KTOT * HDIM;        // [2 buf][2 rowpair][KTOT][4] dup state
    float* red = gb + 2 * 2 * KTOT * 4;   // [NWARP][4 rows][HDIM] partials

    const int tid  = threadIdx.x;
    const int warp = tid >> 5, lane = tid & 31;
    const int chunk = warp & 7;
    const int rp    = warp >> 3;          // 0: rows 0,1   1: rows 2,3
    const int rowbase = blockIdx.x * ROWS;

    // Build k-major combined weight [We_hh | We_ih | 0-pad], zero state bufs
    for (int i = tid; i < KTOT * HDIM; i += 512) {
        int k = i >> 7, j = i & (HDIM - 1);
        float w = 0.f;
        if (k < HDIM)             w = We_hh[j * HDIM + k];
        else if (k < HDIM + VDIM) w = We_ih[j * VDIM + (k - HDIM)];
        Wt[i] = w;
    }
    for (int i = tid; i < 2 * 2 * KTOT * 4; i += 512) gb[i] = 0.f;   // h=0, pads=0
    __syncthreads();

    const int k0 = chunk * KC;
    ull wlo[KC], whi[KC];                 // pre-packed col pairs (80 regs)
    #pragma unroll
    for (int kk = 0; kk < KC; ++kk) {
        const float4 w4 = *(const float4*)(Wt + (k0 + kk) * HDIM + 4 * lane);
        wlo[kk] = pack2(w4.x, w4.y);
        whi[kk] = pack2(w4.z, w4.w);
    }

    // x_0 into buffer 0's x-region (duplicated pairs)
    if (tid < ROWS * VDIM) {
        int r = tid / VDIM, v = tid - r * VDIM;
        float xv = x[((size_t)(rowbase + r) * S_LEN) * VDIM + v];
        *(float2*)(gb + ((r >> 1) * KTOT + HDIM + v) * 4 + 2 * (r & 1)) =
            make_float2(xv, xv);
    }
    __syncthreads();

    // finalize mapping: 512 threads = 128 j x 4 rows; bias in register
    const int jf = tid & (HDIM - 1);
    const int rr = tid >> 7;              // row 0..3
    const float biasr = be_ih[jf] + be_hh[jf];
    const float* redr = red + rr * HDIM + jf;          // + c*4*HDIM per chunk
    float* gout = g_enc + (rowbase + rr) * HDIM + jf;

    // invariant hot-loop pointers
    ull* rb0 = (ull*)(red + (chunk * 4 + rp * 2) * HDIM + 4 * lane);
    ull* rb1 = (ull*)(red + (chunk * 4 + rp * 2 + 1) * HDIM + 4 * lane);
    const float* gkA = gb + (rp * KTOT + k0) * 4;                    // buf 0
    const float* gkB = gkA + 2 * KTOT * 4;                           // buf 1
    float* gwA = gb + ((rr >> 1) * KTOT + jf) * 4 + 2 * (rr & 1);    // buf 0
    float* gwB = gwA + 2 * KTOT * 4;                                 // buf 1

    for (int t = 0; t < S_LEN; ++t) {
        // prefetch next step's x (latency hidden under the GEMV)
        float xr = 0.f; int xslot = -1;
        if (tid < ROWS * VDIM && t + 1 < S_LEN) {
            int r = tid / VDIM, v = tid - r * VDIM;
            xr = x[((size_t)(rowbase + r) * S_LEN + (t + 1)) * VDIM + v];
            xslot = ((t & 1) ^ 1) * (2 * KTOT * 4)
                  + ((r >> 1) * KTOT + HDIM + v) * 4 + 2 * (r & 1);
        }

        ull aL0 = 0, aH0 = 0, aL1 = 0, aH1 = 0;
        const float* gk = (t & 1) ? gkB : gkA;
        #pragma unroll
        for (int kk = 0; kk < KC; ++kk) {
            const ulonglong2 gg = *(const ulonglong2*)(gk + kk * 4);  // 1 LDS.128
            aL0 = fma2(wlo[kk], gg.x, aL0); aH0 = fma2(whi[kk], gg.x, aH0);
            aL1 = fma2(wlo[kk], gg.y, aL1); aH1 = fma2(whi[kk], gg.y, aH1);
        }
        // partials are already in red's layout: (c0,c1,c2,c3) = {aLx, aHx}
        *(ulonglong2*)rb0 = make_ulonglong2(aL0, aH0);   // row rp*2
        *(ulonglong2*)rb1 = make_ulonglong2(aL1, aH1);   // row rp*2+1
        if (xslot >= 0) *(float2*)(gb + xslot) = make_float2(xr, xr);
        __syncthreads();

        // finalize: 512 threads, each sums 8 partials for (jf, rr), tanh
        {
            float s = biasr;
            #pragma unroll
            for (int c = 0; c < NWARP; ++c)
                s += redr[c * 4 * HDIM];
            float h = fast_tanh(s);
            float* gw = (t & 1) ? gwA : gwB;   // write buffer for t+1
            *(float2*)gw = make_float2(h, h);
            if (t == S_LEN - 1) *gout = h;
        }
        __syncthreads();
    }
}

// ---------------------------------------------------------------------------
// Decoder (unchanged, proven): one warp per batch row, 128 CTAs x 4 warps.
// h in per-warp double-buffered SMEM (broadcast LDS.128), 8 FMA accumulators,
// MUFU-based tanh. W row padded to 32 with zeros.
// ---------------------------------------------------------------------------
__global__ void __launch_bounds__(128) dec_kernel(
    const float* __restrict__ Wd_ih, const float* __restrict__ Wd_hh,
    const float* __restrict__ bd_ih, const float* __restrict__ bd_hh,
    float* __restrict__ out)
{
    __shared__ float hbuf[2][4][32];
    const int warp = threadIdx.x >> 5, lane = threadIdx.x & 31;
    const int b = blockIdx.x * 4 + warp;
    const float* er = g_enc + b * HDIM;
    float e0 = er[lane], e1 = er[32 + lane], e2 = er[64 + lane], e3 = er[96 + lane];
    const bool act = lane < VDIM;
    const int vl = act ? lane : 0;

    float Wp[32];
    #pragma unroll
    for (int u = 0; u < 32; ++u) Wp[u] = (u < VDIM) ? Wd_hh[vl * VDIM + u] : 0.f;

    float din = bd_ih[vl] + bd_hh[vl];
    {
        const float* wi = Wd_ih + vl * HDIM;
        float s0 = 0, s1 = 0, s2 = 0, s3 = 0;
        #pragma unroll
        for (int k = 0; k < 32; ++k) {
            s0 += wi[k]      * __shfl_sync(0xffffffffu, e0, k);
            s1 += wi[32 + k] * __shfl_sync(0xffffffffu, e1, k);
            s2 += wi[64 + k] * __shfl_sync(0xffffffffu, e2, k);
            s3 += wi[96 + k] * __shfl_sync(0xffffffffu, e3, k);
        }
        din += (s0 + s1) + (s2 + s3);
    }

    hbuf[0][warp][lane] = 0.f;
    __syncwarp();

    float* orow = out + (size_t)b * S_LEN * VDIM + lane;
    for (int s = 0; s < S_LEN; ++s) {
        const float* hv = hbuf[s & 1][warp];
        const float4 A = *(const float4*)(hv);
        const float4 B = *(const float4*)(hv + 4);
        const float4 C = *(const float4*)(hv + 8);
        const float4 D = *(const float4*)(hv + 12);
        const float4 E = *(const float4*)(hv + 16);
        const float4 F = *(const float4*)(hv + 20);
        const float4 G = *(const float4*)(hv + 24);
        const float4 H = *(const float4*)(hv + 28);
        float q0 = fmaf(Wp[0],  A.x, din), q1 = Wp[1]  * A.y;
        float q2 = Wp[2]  * A.z,           q3 = Wp[3]  * A.w;
        float q4 = Wp[4]  * B.x,           q5 = Wp[5]  * B.y;
        float q6 = Wp[6]  * B.z,           q7 = Wp[7]  * B.w;
        q0 = fmaf(Wp[8],  C.x, q0); q1 = fmaf(Wp[9],  C.y, q1);
        q2 = fmaf(Wp[10], C.z, q2); q3 = fmaf(Wp[11], C.w, q3);
        q4 = fmaf(Wp[12], D.x, q4); q5 = fmaf(Wp[13], D.y, q5);
        q6 = fmaf(Wp[14], D.z, q6); q7 = fmaf(Wp[15], D.w, q7);
        q0 = fmaf(Wp[16], E.x, q0); q1 = fmaf(Wp[17], E.y, q1);
        q2 = fmaf(Wp[18], E.z, q2); q3 = fmaf(Wp[19], E.w, q3);
        q4 = fmaf(Wp[20], F.x, q4); q5 = fmaf(Wp[21], F.y, q5);
        q6 = fmaf(Wp[22], F.z, q6); q7 = fmaf(Wp[23], F.w, q7);
        q0 = fmaf(Wp[24], G.x, q0); q1 = fmaf(Wp[25], G.y, q1);
        q2 = fmaf(Wp[26], G.z, q2); q3 = fmaf(Wp[27], G.w, q3);
        q4 = fmaf(Wp[28], H.x, q4); q5 = fmaf(Wp[29], H.y, q5);
        q6 = fmaf(Wp[30], H.z, q6); q7 = fmaf(Wp[31], H.w, q7);
        float hn = fast_tanh(((q0 + q1) + (q2 + q3)) + ((q4 + q5) + (q6 + q7)));
        hbuf[(s & 1) ^ 1][warp][lane] = hn;
        if (act) orow[(size_t)s * VDIM] = hn;
        __syncwarp();
    }
}

// ---------------------------------------------------------------------------
extern "C" void kernel_launch(void* const* d_in, const int* in_sizes, int n_in,
                              void* d_out, int out_size) {
    const float* x     = (const float*)d_in[0];
    const float* We_ih = (const float*)d_in[1];
    const float* We_hh = (const float*)d_in[2];
    const float* be_ih = (const float*)d_in[3];
    const float* be_hh = (const float*)d_in[4];
    const float* Wd_ih = (const float*)d_in[5];
    const float* Wd_hh = (const float*)d_in[6];
    const float* bd_ih = (const float*)d_in[7];
    const float* bd_hh = (const float*)d_in[8];
    float* out = (float*)d_out;

    const int smem = (KTOT * HDIM + 2 * 2 * KTOT * 4 + NWARP * 4 * HDIM) * 4; // 108544 B
    cudaFuncSetAttribute(enc_kernel, cudaFuncAttributeMaxDynamicSharedMemorySize, smem);

    enc_kernel<<<BATCH / ROWS, 512, smem>>>(x, We_ih, We_hh, be_ih, be_hh);
    dec_kernel<<<BATCH / 4, 128>>>(Wd_ih, Wd_hh, bd_ih, bd_hh, out);
}